// round 11
// baseline (speedup 1.0000x reference)
#include <cuda_runtime.h>
#include <cuda_fp16.h>
#include <cstdint>
#include <cstddef>

// VQ nearest-neighbor quantization via mma.sync fp16 2-split (ah*bh + ah*bl),
// exact argmin via unmerged slot top-2 + fp64 near-tie refinement.
// x: [32,64,64,64] f32 (B,C,H,W), codebook: [512,64] f32
// out: codes [B,C,H,W] f32 (8388608) then indices [B,H,W] as f32 (131072)

#define KCODES 512
#define DCH    64
#define BATCH  32
#define HH     64
#define WW     64
#define THREADS 512
#define POS     128
#define NTILES  (BATCH*(HH/2))   // 1024
#define BIAS    512.0f
#define MARGIN  0.05f
#define XSTR    68               // xs row stride (floats)

#define CODES_ELEMS ((size_t)BATCH*DCH*HH*WW)
#define IDX_ELEMS   ((size_t)BATCH*HH*WW)

// ---- smem byte offsets from 1024-aligned base ----
#define A_HI_OFF 0            // [128][128B] fp16 SW128 (x hi)
#define B_HI_OFF 16384        // [512][128B] fp16 SW128 (cb hi)
#define B_LO_OFF 81920        // [512][128B] fp16 SW128 (cb lo)
#define XS_OFF   147456       // float[128][68] exact x tile
#define HB_OFF   182272       // float[512] BIAS - 0.5||c||^2
#define BKS_OFF  184320       // u32[128][17] slot best keys
#define SKS_OFF  193024       // u32[128][17] slot second keys
#define IDXS_OFF 201728       // int[128]
#define SMEM_BYTES (202240 + 1024)

#define SW(o) ((o) ^ (((o) >> 3) & 0x70))

typedef uint32_t u32;

static __device__ __forceinline__ u32 smem_u32(const void* p) {
    u32 a;
    asm("{ .reg .u64 t; cvta.to.shared.u64 t, %1; cvt.u32.u64 %0, t; }" : "=r"(a) : "l"(p));
    return a;
}
static __device__ __forceinline__ u32 pack_h2(float a, float b) {
    __half ha = __float2half(a), hb2 = __float2half(b);
    return (u32)__half_as_ushort(ha) | ((u32)__half_as_ushort(hb2) << 16);
}

#define LDSM_X4(r0,r1,r2,r3, addr) \
    asm volatile("ldmatrix.sync.aligned.m8n8.x4.shared.b16 {%0,%1,%2,%3}, [%4];" \
        : "=r"(r0),"=r"(r1),"=r"(r2),"=r"(r3) : "r"(addr))

#define MMA16816(d, a, b0, b1) \
    asm volatile("mma.sync.aligned.m16n8k16.row.col.f32.f16.f16.f32 " \
        "{%0,%1,%2,%3}, {%4,%5,%6,%7}, {%8,%9}, {%0,%1,%2,%3};" \
        : "+f"((d)[0]),"+f"((d)[1]),"+f"((d)[2]),"+f"((d)[3]) \
        : "r"((a)[0]),"r"((a)[1]),"r"((a)[2]),"r"((a)[3]), "r"(b0),"r"(b1))

// key -> code index; slot = wn*4 + q
static __device__ __forceinline__ int key_to_k(u32 key, int slot) {
    int j5 = 31 - (int)(key & 31u);
    int wn_ = slot >> 2, q_ = slot & 3;
    return 128*wn_ + (j5 >> 3)*32 + ((j5 >> 1) & 3)*8 + 2*q_ + (j5 & 1);
}

__global__ __launch_bounds__(THREADS, 1)
void vq_kernel(const float* __restrict__ x, const float* __restrict__ cb,
               float* __restrict__ out, int write_idx)
{
    extern __shared__ char smraw[];
    const u32 sb0 = smem_u32(smraw);
    const u32 sb  = (sb0 + 1023u) & ~1023u;
    char* base = smraw + (sb - sb0);

    float* xs   = (float*)(base + XS_OFF);
    float* hb   = (float*)(base + HB_OFF);
    u32*   bKs  = (u32*)  (base + BKS_OFF);
    u32*   sKs  = (u32*)  (base + SKS_OFF);
    int*   idxs = (int*)  (base + IDXS_OFF);

    const int tid  = threadIdx.x;
    const int wid  = tid >> 5;
    const int lane = tid & 31;
    const int wm   = wid & 3;    // M group: positions 32*wm..+31
    const int wn   = wid >> 2;   // N group: codes 128*wn..+127
    const int q    = lane & 3;   // column pair within C frag

    // per-lane ldmatrix geometry (non-trans, proven in round 10)
    const int a_row = (lane & 7) + ((lane >> 3) & 1) * 8;
    const int a_kb  = (lane >> 4) & 1;
    const int b_row = (lane & 7) + ((lane >> 4) & 1) * 8;
    const int b_kb  = (lane >> 3) & 1;
    const u32 xorL  = (u32)((lane & 7) << 4);

    // ---- one-time: codebook -> fp16 hi/lo swizzled SMEM ----
    for (int it = 0; it < 16; it++) {
        int idx = tid + it * THREADS;        // 8192 items: (k, cgroup)
        int k  = idx >> 4;
        int c0 = (idx & 15) * 4;
        float4 v = *(const float4*)(cb + (size_t)k * DCH + c0);
        float hx = __half2float(__float2half(v.x));
        float hy = __half2float(__float2half(v.y));
        float hz = __half2float(__float2half(v.z));
        float hw = __half2float(__float2half(v.w));
        u32 hi0 = pack_h2(v.x, v.y), hi1 = pack_h2(v.z, v.w);
        u32 lo0 = pack_h2(v.x - hx, v.y - hy), lo1 = pack_h2(v.z - hz, v.w - hw);
        u32 o = (u32)(k * 128) + (u32)((c0 * 2) ^ ((k & 7) << 4));
        *(uint2*)(base + B_HI_OFF + o) = make_uint2(hi0, hi1);
        *(uint2*)(base + B_LO_OFF + o) = make_uint2(lo0, lo1);
    }
    if (tid < KCODES) {
        float s = 0.f;
        #pragma unroll
        for (int c = 0; c < DCH; c++) { float v = cb[(size_t)tid * DCH + c]; s += v * v; }
        hb[tid] = BIAS - 0.5f * s;
    }
    __syncthreads();

    for (int tile = blockIdx.x; tile < NTILES; tile += gridDim.x) {
        const int b  = tile >> 5;
        const int h0 = (tile & 31) * 2;
        __syncthreads();  // previous tile's smem reads complete

        // ---- stage pass 1: global -> exact xs (coalesced) ----
        for (int it = 0; it < 16; it++) {
            int i = tid + it * THREADS;     // 8192 = 64c * 128p
            int c = i >> 7, p = i & 127;
            int hl = p >> 6, w = p & 63;
            xs[p * XSTR + c] = x[((((size_t)b * DCH + c) * HH) + h0 + hl) * WW + w];
        }
        __syncthreads();

        // ---- stage pass 2: xs -> fp16 hi swizzled A ----
        for (int it = 0; it < 4; it++) {
            int idx = tid + it * THREADS;    // 2048 = 128p * 16 cgroups
            int p  = idx >> 4;
            int c0 = (idx & 15) * 4;
            float4 v = *(const float4*)(xs + p * XSTR + c0);
            u32 hi0 = pack_h2(v.x, v.y), hi1 = pack_h2(v.z, v.w);
            u32 o = (u32)(p * 128) + (u32)((c0 * 2) ^ ((p & 7) << 4));
            *(uint2*)(base + A_HI_OFF + o) = make_uint2(hi0, hi1);
        }
        __syncthreads();

        // ---- mainloop: 4 chunks x (A once + 2 B-splits); slot top-2 keys ----
        u32 bK[4] = {0u,0u,0u,0u};
        u32 sK[4] = {0u,0u,0u,0u};
        const int m0  = 32 * wm;
        const int nb0 = 128 * wn;

        #pragma unroll
        for (int chunk = 0; chunk < 4; chunk++) {
            float acc[4][2][4];
            #pragma unroll
            for (int ntc = 0; ntc < 4; ntc++) {
                float2 h2 = *(const float2*)(hb + nb0 + chunk * 32 + ntc * 8 + 2 * q);
                #pragma unroll
                for (int mt = 0; mt < 2; mt++) {
                    acc[ntc][mt][0] = h2.x; acc[ntc][mt][1] = h2.y;
                    acc[ntc][mt][2] = h2.x; acc[ntc][mt][3] = h2.y;
                }
            }

            // A fragments once per chunk (shared by both splits)
            u32 a[2][4][4];
            #pragma unroll
            for (int mt = 0; mt < 2; mt++)
                #pragma unroll
                for (int ks = 0; ks < 4; ks++) {
                    u32 colb = (u32)(ks * 32 + a_kb * 16) ^ xorL;
                    u32 ad = sb + A_HI_OFF + (u32)((m0 + mt * 16 + a_row) * 128) + colb;
                    LDSM_X4(a[mt][ks][0], a[mt][ks][1], a[mt][ks][2], a[mt][ks][3], ad);
                }

            #pragma unroll
            for (int split = 0; split < 2; split++) {
                const u32 Bb = sb + (split ? B_LO_OFF : B_HI_OFF);
                #pragma unroll
                for (int np = 0; np < 2; np++) {
                    const int n0 = nb0 + chunk * 32 + np * 16;
                    #pragma unroll
                    for (int ks = 0; ks < 4; ks++) {
                        u32 b0, b1, b2, b3;
                        u32 colb = (u32)(ks * 32 + b_kb * 16) ^ xorL;
                        u32 bd = Bb + (u32)((n0 + b_row) * 128) + colb;
                        LDSM_X4(b0, b1, b2, b3, bd);
                        #pragma unroll
                        for (int mt = 0; mt < 2; mt++) {
                            MMA16816(acc[np*2+0][mt], a[mt][ks], b0, b1);
                            MMA16816(acc[np*2+1][mt], a[mt][ks], b2, b3);
                        }
                    }
                }
            }

            // chunk scoring: quantized keys + branchless slot top-2
            #pragma unroll
            for (int ntc = 0; ntc < 4; ntc++) {
                const int nt = chunk * 4 + ntc;
                const u32 jrL = (u32)(31 - (nt * 2 + 0));
                const u32 jrH = (u32)(31 - (nt * 2 + 1));
                #pragma unroll
                for (int mt = 0; mt < 2; mt++) {
                    u32 k0b = (__float_as_uint(acc[ntc][mt][0]) & ~31u) | jrL;
                    u32 k1b = (__float_as_uint(acc[ntc][mt][1]) & ~31u) | jrH;
                    u32 k2b = (__float_as_uint(acc[ntc][mt][2]) & ~31u) | jrL;
                    u32 k3b = (__float_as_uint(acc[ntc][mt][3]) & ~31u) | jrH;
                    int sA = mt * 2, sB = mt * 2 + 1;
                    sK[sA] = umax(sK[sA], umin(bK[sA], k0b)); bK[sA] = umax(bK[sA], k0b);
                    sK[sA] = umax(sK[sA], umin(bK[sA], k1b)); bK[sA] = umax(bK[sA], k1b);
                    sK[sB] = umax(sK[sB], umin(bK[sB], k2b)); bK[sB] = umax(bK[sB], k2b);
                    sK[sB] = umax(sK[sB], umin(bK[sB], k3b)); bK[sB] = umax(bK[sB], k3b);
                }
            }
        }

        // ---- write per-slot top-2 keys (no merge) ----
        #pragma unroll
        for (int s = 0; s < 4; s++) {
            int p = 32 * wm + (lane >> 2) + s * 8;
            bKs[p * 17 + wn * 4 + q] = bK[s];
            sKs[p * 17 + wn * 4 + q] = sK[s];
        }
        __syncthreads();

        // ---- refinement: scan 32 candidates, fp64-arbitrate near-ties ----
        if (tid < POS) {
            const int p = tid;
            u32 km = 0; int im = 0;
            for (int i = 0; i < 16; i++) {
                u32 kk = bKs[p*17 + i]; if (kk > km) { km = kk; im = i; }
            }
            for (int i = 0; i < 16; i++) {
                u32 kk = sKs[p*17 + i]; if (kk > km) { km = kk; im = i; }
            }
            float vthr = __uint_as_float(km & ~31u) - BIAS - MARGIN;
            int nf = 0;
            for (int i = 0; i < 32; i++) {
                u32 kk = (i < 16) ? bKs[p*17 + i] : sKs[p*17 + (i-16)];
                if (__uint_as_float(kk & ~31u) - BIAS >= vthr) nf++;
            }
            int bi;
            if (nf <= 1) {
                bi = key_to_k(km, im);
            } else {
                double bd = 1.0e300; bi = 0x7fffffff;
                for (int i = 0; i < 32; i++) {
                    u32 kk = (i < 16) ? bKs[p*17 + i] : sKs[p*17 + (i-16)];
                    if (__uint_as_float(kk & ~31u) - BIAS < vthr) continue;
                    int k = key_to_k(kk, i & 15);
                    const float* crow = cb + (size_t)k * DCH;
                    double d = 0.0;
                    for (int c = 0; c < DCH; c++) {
                        double e = (double)xs[p * XSTR + c] - (double)__ldg(crow + c);
                        d += e * e;
                    }
                    if (d < bd || (d == bd && k < bi)) { bd = d; bi = k; }
                }
            }
            idxs[p] = bi;
        }
        __syncthreads();

        // ---- epilogue: codes = fp16 hi+lo reconstruction (rel err ~1e-7) ----
        for (int i4 = tid; i4 < (DCH*POS)/4; i4 += THREADS) {
            int c  = i4 >> 5;
            int p  = (i4 & 31) * 4;
            int hl = p >> 6, w = p & 63;
            float4 v;
            #pragma unroll
            for (int e = 0; e < 4; e++) {
                int k = idxs[p + e];
                u32 off = SW((u32)(k * 128 + c * 2));
                float hv = __half2float(*(const __half*)(base + B_HI_OFF + off));
                float lv = __half2float(*(const __half*)(base + B_LO_OFF + off));
                ((float*)&v)[e] = hv + lv;
            }
            *(float4*)(out + (((size_t)b * DCH + c) * HH + h0 + hl) * WW + w) = v;
        }
        if (write_idx && tid < POS) {
            int hl = tid >> 6, w = tid & 63;
            out[CODES_ELEMS + ((size_t)b * HH + h0 + hl) * WW + w] = (float)idxs[tid];
        }
    }
}

extern "C" void kernel_launch(void* const* d_in, const int* in_sizes, int n_in,
                              void* d_out, int out_size)
{
    const float* x  = (const float*)d_in[0];
    const float* cb = (const float*)d_in[1];
    float* out = (float*)d_out;

    int write_idx = ((size_t)out_size >= CODES_ELEMS + IDX_ELEMS) ? 1 : 0;

    int dev = 0;
    cudaGetDevice(&dev);
    int sms = 0;
    cudaDeviceGetAttribute(&sms, cudaDevAttrMultiProcessorCount, dev);
    if (sms <= 0) sms = 148;
    if (sms > NTILES) sms = NTILES;

    cudaFuncSetAttribute(vq_kernel, cudaFuncAttributeMaxDynamicSharedMemorySize,
                         (int)SMEM_BYTES);
    vq_kernel<<<sms, THREADS, SMEM_BYTES>>>(x, cb, out, write_idx);
}